// round 1
// baseline (speedup 1.0000x reference)
#include <cuda_runtime.h>
#include <math.h>

// ---------------- problem constants ----------------
#define NIN    20000          // B_AG * N_PTS
#define CINCH  64
#define C0CH   32
#define C1CH   64
#define CAP0   540000         // 27 * NIN
#define CAP1   352000         // B_AG * Z1*Y1*X1
#define ZD     10
#define YD     200
#define XD     704
#define Z1D    5
#define Y1D    100
#define X1D    352
#define HW     (YD*XD)        // 140800
#define HW1    (Y1D*X1D)      // 35200
#define EPSB   1e-5f

// ---------------- static device scratch (no allocations allowed) ----------------
__device__ float g_fin [NIN * C0CH];                 // 2.56 MB
__device__ float g_f0a [(CAP0 + 1) * C0CH];          // 69 MB
__device__ float g_f0b [(CAP0 + 1) * C0CH];          // 69 MB
__device__ float g_f1a [(CAP1 + 1) * C1CH];          // 90 MB
__device__ float g_f1b [(CAP1 + 1) * C1CH];          // 90 MB
__device__ float g_d0  [2 * HW  * 320];              // 360 MB  layout [b*HW+p][z*32+c]
__device__ float g_d1  [2 * HW1 * 320];              // 90 MB   layout [b*HW1+p][z*64+c]
__device__ float g_bev0[2 * 64 * HW];                // 72 MB   [b*64+o][p]
__device__ float g_bev1[2 * 64 * HW];                // 72 MB
__device__ float g_w0p [320 * 64];                   // permuted ct0_w
__device__ float g_w1p [4 * 320 * 64];               // permuted ct1_w [ij][kk][o]

// ---------------- kernels ----------------

// fin = sp_feats[NIN,64] @ w_in[64,32]
__global__ void k_gemm_in(const float* __restrict__ sp, const float* __restrict__ w,
                          float* __restrict__ out) {
    int t = blockIdx.x * blockDim.x + threadIdx.x;
    if (t >= NIN * 32) return;
    int i = t >> 5, j = t & 31;
    const float* r = sp + i * 64;
    float acc = 0.f;
#pragma unroll
    for (int c = 0; c < 64; c++) acc += r[c] * w[c * 32 + j];
    out[t] = acc;
}

// gather-GEMM-scatter: one warp per (k,pair). Dummy pairs (s>=out_cap) early-exit.
template<int CIN, int COUT>
__global__ void k_spconv(const float* __restrict__ feats,
                         const int* __restrict__ G, const int* __restrict__ S,
                         const float* __restrict__ W, float* __restrict__ out,
                         int pair_cap, int out_cap) {
    unsigned wid = (blockIdx.x * blockDim.x + threadIdx.x) >> 5;
    int lane = threadIdx.x & 31;
    if (wid >= (unsigned)(27 * pair_cap)) return;
    int s = S[wid];
    if (s >= out_cap) return;
    int g = G[wid];
    int k = wid / pair_cap;
    const float* Wk = W + (size_t)k * CIN * COUT;
    const float* fr = feats + (size_t)g * CIN;
    float fv[CIN / 32];
#pragma unroll
    for (int r = 0; r < CIN / 32; r++) fv[r] = fr[lane + 32 * r];
    float acc[COUT / 32];
#pragma unroll
    for (int r = 0; r < COUT / 32; r++) acc[r] = 0.f;
#pragma unroll
    for (int c = 0; c < CIN; c++) {
        float v = __shfl_sync(0xffffffffu, fv[c >> 5], c & 31);
#pragma unroll
        for (int r = 0; r < COUT / 32; r++)
            acc[r] += v * Wk[c * COUT + lane + 32 * r];
    }
    float* orow = out + (size_t)s * COUT;
#pragma unroll
    for (int r = 0; r < COUT / 32; r++) atomicAdd(&orow[lane + 32 * r], acc[r]);
}

// in-place BN1d + ReLU over rows*C elements; bn layout [4][C] = g,b,m,v
__global__ void k_bnrelu(float* __restrict__ buf, const float* __restrict__ bn,
                         int rows, int C) {
    long long idx = (long long)blockIdx.x * blockDim.x + threadIdx.x;
    if (idx >= (long long)rows * C) return;
    int c = (int)(idx & (C - 1));          // C is 32 or 64
    float gg = bn[c], bb = bn[C + c], m = bn[2 * C + c], v = bn[3 * C + c];
    float x = buf[idx];
    float y = (x - m) * (gg * rsqrtf(v + EPSB)) + bb;
    buf[idx] = y > 0.f ? y : 0.f;
}

// scatter sparse features into dense d0 [b*HW+p][z*32+c]; warp per row
__global__ void k_scatter0(const float* __restrict__ f, const int* __restrict__ co,
                           float* __restrict__ d0) {
    unsigned w = (blockIdx.x * blockDim.x + threadIdx.x) >> 5;
    int lane = threadIdx.x & 31;
    if (w >= CAP0) return;
    int z = co[4 * w + 1];
    if ((unsigned)z >= (unsigned)ZD) return;   // padding rows have z==ZD
    int b = co[4 * w], y = co[4 * w + 2], x = co[4 * w + 3];
    size_t base = ((size_t)(b * HW + y * XD + x)) * 320 + z * 32;
    d0[base + lane] = f[(size_t)w * 32 + lane];
}

__global__ void k_scatter1(const float* __restrict__ f, const int* __restrict__ co,
                           float* __restrict__ d1) {
    unsigned w = (blockIdx.x * blockDim.x + threadIdx.x) >> 5;
    int lane = threadIdx.x & 31;
    if (w >= CAP1) return;
    int z = co[4 * w + 1];
    if ((unsigned)z >= (unsigned)Z1D) return;
    int b = co[4 * w], y = co[4 * w + 2], x = co[4 * w + 3];
    size_t base = ((size_t)(b * HW1 + y * X1D + x)) * 320 + z * 64;
    d1[base + lane]      = f[(size_t)w * 64 + lane];
    d1[base + lane + 32] = f[(size_t)w * 64 + lane + 32];
}

// permute ct0_w [cin=c*10+z][64] -> wp[kk=z*32+c][64]
__global__ void k_permw0(const float* __restrict__ w, float* __restrict__ wp) {
    int t = blockIdx.x * blockDim.x + threadIdx.x;
    if (t >= 320 * 64) return;
    int o = t & 63, kk = t >> 6;
    int z = kk >> 5, c = kk & 31;
    wp[t] = w[(c * 10 + z) * 64 + o];
}

// permute ct1_w [cin=c*5+z][64][2][2] -> wp[ij][kk=z*64+c][64]
__global__ void k_permw1(const float* __restrict__ w, float* __restrict__ wp) {
    int t = blockIdx.x * blockDim.x + threadIdx.x;
    if (t >= 4 * 320 * 64) return;
    int o  = t & 63;
    int kk = (t >> 6) % 320;
    int ij = (t >> 6) / 320;
    int z = kk >> 6, c = kk & 63;
    wp[t] = w[((c * 5 + z) * 64 + o) * 4 + ij];
}

// 1x1 conv (320->64) + BN2d + ReLU -> bev0 [b*64+o][p].  blockDim = (64,4)
__global__ void k_conv1x1(const float* __restrict__ d0, const float* __restrict__ wp,
                          const float* __restrict__ bias, const float* __restrict__ bn,
                          float* __restrict__ bev) {
    int o  = threadIdx.x;
    int pg = blockIdx.x * blockDim.y + threadIdx.y;
    if (pg >= 2 * HW) return;
    const float* row = d0 + (size_t)pg * 320;
    float acc = bias[o];
#pragma unroll 8
    for (int kk = 0; kk < 320; kk++) acc += row[kk] * wp[kk * 64 + o];
    float gg = bn[o], bb = bn[64 + o], m = bn[128 + o], v = bn[192 + o];
    float y = (acc - m) * (gg * rsqrtf(v + EPSB)) + bb;
    y = fmaxf(y, 0.f);
    int b = pg >= HW;
    int p = pg - b * HW;
    bev[(size_t)(b * 64 + o) * HW + p] = y;
}

// ConvTranspose2d k=2 s=2 (each output pixel hits exactly one input pixel)
__global__ void k_convt(const float* __restrict__ d1, const float* __restrict__ wp,
                        const float* __restrict__ bias, const float* __restrict__ bn,
                        float* __restrict__ bev) {
    int o  = threadIdx.x;
    int pg = blockIdx.x * blockDim.y + threadIdx.y;
    if (pg >= 2 * HW) return;
    int b  = pg >= HW;
    int P  = pg - b * HW;
    int Py = P / XD, Px = P % XD;
    int ij = (Py & 1) * 2 + (Px & 1);
    const float* row = d1 + ((size_t)(b * HW1 + (Py >> 1) * X1D + (Px >> 1))) * 320;
    const float* wij = wp + ij * 320 * 64;
    float acc = bias[o];
#pragma unroll 8
    for (int kk = 0; kk < 320; kk++) acc += row[kk] * wij[kk * 64 + o];
    float gg = bn[o], bb = bn[64 + o], m = bn[128 + o], v = bn[192 + o];
    float y = (acc - m) * (gg * rsqrtf(v + EPSB)) + bb;
    y = fmaxf(y, 0.f);
    bev[(size_t)(b * 64 + o) * HW + P] = y;
}

// per-pixel 2-agent scaled dot-product attention, keep agent 0
__global__ void k_fusion(const float* __restrict__ bev, float* __restrict__ out, int cbase) {
    int p = blockIdx.x * blockDim.x + threadIdx.x;
    if (p >= HW) return;
    float l00 = 0.f, l01 = 0.f;
#pragma unroll 8
    for (int c = 0; c < 64; c++) {
        float x0 = bev[c * HW + p];
        float x1 = bev[(64 + c) * HW + p];
        l00 += x0 * x0;
        l01 += x0 * x1;
    }
    l00 *= 0.125f;  l01 *= 0.125f;          // 1/sqrt(64)
    float mm = fmaxf(l00, l01);
    float e0 = expf(l00 - mm), e1 = expf(l01 - mm);
    float inv = 1.f / (e0 + e1);
    float a0 = e0 * inv, a1 = e1 * inv;
#pragma unroll 8
    for (int c = 0; c < 64; c++) {
        float x0 = bev[c * HW + p];
        float x1 = bev[(64 + c) * HW + p];
        out[(size_t)(cbase + c) * HW + p] = a0 * x0 + a1 * x1;
    }
}

// ---------------- host launcher ----------------
static inline unsigned blocks_for(long long threads, int bs) {
    return (unsigned)((threads + bs - 1) / bs);
}

extern "C" void kernel_launch(void* const* d_in, const int* in_sizes, int n_in,
                              void* d_out, int out_size) {
    const float* sp     = (const float*)d_in[0];
    const float* w_in   = (const float*)d_in[1];
    const float* w0     = (const float*)d_in[2];
    const float* bnp0   = (const float*)d_in[3];
    const float* w0a    = (const float*)d_in[4];
    const float* bnp0a  = (const float*)d_in[5];
    const float* w0b    = (const float*)d_in[6];
    const float* bnp0b  = (const float*)d_in[7];
    const float* w1     = (const float*)d_in[8];
    const float* bnp1   = (const float*)d_in[9];
    const float* w1a    = (const float*)d_in[10];
    const float* bnp1a  = (const float*)d_in[11];
    const float* w1b    = (const float*)d_in[12];
    const float* bnp1b  = (const float*)d_in[13];
    const float* ct0_w  = (const float*)d_in[14];
    const float* ct0_b  = (const float*)d_in[15];
    const float* bnt0   = (const float*)d_in[16];
    const float* ct1_w  = (const float*)d_in[17];
    const float* ct1_b  = (const float*)d_in[18];
    const float* bnt1   = (const float*)d_in[19];
    const int* coords0  = (const int*)d_in[20];
    const int* coords1  = (const int*)d_in[21];
    const int* g0       = (const int*)d_in[22];
    const int* s0       = (const int*)d_in[23];
    const int* ga       = (const int*)d_in[24];
    const int* sa       = (const int*)d_in[25];
    const int* g1       = (const int*)d_in[26];
    const int* s1       = (const int*)d_in[27];
    const int* gb       = (const int*)d_in[28];
    const int* sb       = (const int*)d_in[29];
    float* out = (float*)d_out;

    float *fin, *f0a, *f0b, *f1a, *f1b, *d0, *d1, *bev0, *bev1, *w0p, *w1p;
    cudaGetSymbolAddress((void**)&fin,  g_fin);
    cudaGetSymbolAddress((void**)&f0a,  g_f0a);
    cudaGetSymbolAddress((void**)&f0b,  g_f0b);
    cudaGetSymbolAddress((void**)&f1a,  g_f1a);
    cudaGetSymbolAddress((void**)&f1b,  g_f1b);
    cudaGetSymbolAddress((void**)&d0,   g_d0);
    cudaGetSymbolAddress((void**)&d1,   g_d1);
    cudaGetSymbolAddress((void**)&bev0, g_bev0);
    cudaGetSymbolAddress((void**)&bev1, g_bev1);
    cudaGetSymbolAddress((void**)&w0p,  g_w0p);
    cudaGetSymbolAddress((void**)&w1p,  g_w1p);

    const int BS = 256;

    // ---- input GEMM ----
    k_gemm_in<<<blocks_for((long long)NIN * 32, BS), BS>>>(sp, w_in, fin);

    // ---- stage 0: spconv (stride1) + 2x subm, C=32 ----
    cudaMemsetAsync(f0a, 0, (size_t)(CAP0 + 1) * 32 * sizeof(float), 0);
    k_spconv<32, 32><<<blocks_for(27LL * NIN * 32, BS), BS>>>(fin, g0, s0, w0, f0a, NIN, CAP0);
    k_bnrelu<<<blocks_for((long long)CAP0 * 32, BS), BS>>>(f0a, bnp0, CAP0, 32);

    cudaMemsetAsync(f0b, 0, (size_t)(CAP0 + 1) * 32 * sizeof(float), 0);
    k_spconv<32, 32><<<blocks_for(27LL * CAP0 * 32, BS), BS>>>(f0a, ga, sa, w0a, f0b, CAP0, CAP0);
    k_bnrelu<<<blocks_for((long long)CAP0 * 32, BS), BS>>>(f0b, bnp0a, CAP0, 32);

    cudaMemsetAsync(f0a, 0, (size_t)(CAP0 + 1) * 32 * sizeof(float), 0);
    k_spconv<32, 32><<<blocks_for(27LL * CAP0 * 32, BS), BS>>>(f0b, ga, sa, w0b, f0a, CAP0, CAP0);
    k_bnrelu<<<blocks_for((long long)CAP0 * 32, BS), BS>>>(f0a, bnp0b, CAP0, 32);

    // ---- dense BEV 0 ----
    cudaMemsetAsync(d0, 0, (size_t)2 * HW * 320 * sizeof(float), 0);
    k_scatter0<<<blocks_for((long long)CAP0 * 32, BS), BS>>>(f0a, coords0, d0);
    k_permw0<<<blocks_for(320 * 64, BS), BS>>>(ct0_w, w0p);
    dim3 bt(64, 4);
    k_conv1x1<<<blocks_for(2LL * HW, 4), bt>>>(d0, w0p, ct0_b, bnt0, bev0);
    k_fusion<<<blocks_for(HW, BS), BS>>>(bev0, out, 0);

    // ---- stage 1: spconv (stride2, 32->64) + 2x subm (64->64) ----
    cudaMemsetAsync(f1a, 0, (size_t)(CAP1 + 1) * 64 * sizeof(float), 0);
    k_spconv<32, 64><<<blocks_for(27LL * CAP0 * 32, BS), BS>>>(f0a, g1, s1, w1, f1a, CAP0, CAP1);
    k_bnrelu<<<blocks_for((long long)CAP1 * 64, BS), BS>>>(f1a, bnp1, CAP1, 64);

    cudaMemsetAsync(f1b, 0, (size_t)(CAP1 + 1) * 64 * sizeof(float), 0);
    k_spconv<64, 64><<<blocks_for(27LL * CAP1 * 32, BS), BS>>>(f1a, gb, sb, w1a, f1b, CAP1, CAP1);
    k_bnrelu<<<blocks_for((long long)CAP1 * 64, BS), BS>>>(f1b, bnp1a, CAP1, 64);

    cudaMemsetAsync(f1a, 0, (size_t)(CAP1 + 1) * 64 * sizeof(float), 0);
    k_spconv<64, 64><<<blocks_for(27LL * CAP1 * 32, BS), BS>>>(f1b, gb, sb, w1b, f1a, CAP1, CAP1);
    k_bnrelu<<<blocks_for((long long)CAP1 * 64, BS), BS>>>(f1a, bnp1b, CAP1, 64);

    // ---- dense BEV 1 ----
    cudaMemsetAsync(d1, 0, (size_t)2 * HW1 * 320 * sizeof(float), 0);
    k_scatter1<<<blocks_for((long long)CAP1 * 32, BS), BS>>>(f1a, coords1, d1);
    k_permw1<<<blocks_for(4 * 320 * 64, BS), BS>>>(ct1_w, w1p);
    k_convt<<<blocks_for(2LL * HW, 4), bt>>>(d1, w1p, ct1_b, bnt1, bev1);
    k_fusion<<<blocks_for(HW, BS), BS>>>(bev1, out, 64);
}

// round 2
// speedup vs baseline: 1.7969x; 1.7969x over previous
#include <cuda_runtime.h>
#include <math.h>

// ---------------- problem constants ----------------
#define NIN    20000          // B_AG * N_PTS
#define CAP0   540000         // 27 * NIN
#define CAP1   352000         // B_AG * Z1*Y1*X1
#define ZD     10
#define YD     200
#define XD     704
#define Z1D    5
#define Y1D    100
#define X1D    352
#define HW     (YD*XD)        // 140800
#define HW1    (Y1D*X1D)      // 35200
#define EPSB   1e-5f

// ---------------- static device scratch ----------------
__device__ float g_fin [NIN * 32];
__device__ float g_f0a [(CAP0 + 1) * 32];
__device__ float g_f0b [(CAP0 + 1) * 32];
__device__ float g_f1a [(CAP1 + 1) * 64];
__device__ float g_f1b [(CAP1 + 1) * 64];
__device__ float g_d0  [2 * HW  * 320];              // [b*HW+p][z*32+c]
__device__ float g_d1  [2 * HW1 * 320];              // [b*HW1+p][z*64+c]
__device__ float g_bev0[2 * 64 * HW];                // [b*64+o][p]
__device__ float g_bev1[2 * 64 * HW];
__device__ float g_w0p [320 * 64];                   // B for conv1x1 GEMM
__device__ float g_w1p [320 * 256];                  // B for convt GEMM [kk][ij*64+o]
__device__ int   g_cnt [108];                        // per-k real pair counts, 4 rulebooks

// ---------------- rulebook pair counts (binary search on padded suffix) ----------------
__global__ void k_counts(const int* __restrict__ s0, const int* __restrict__ sa,
                         const int* __restrict__ s1, const int* __restrict__ sb) {
    int t = blockIdx.x * blockDim.x + threadIdx.x;
    if (t >= 108) return;
    int rb = t / 27, k = t % 27;
    const int* S; int pc, cap;
    if      (rb == 0) { S = s0; pc = NIN;  cap = CAP0; }
    else if (rb == 1) { S = sa; pc = CAP0; cap = CAP0; }
    else if (rb == 2) { S = s1; pc = CAP0; cap = CAP1; }
    else              { S = sb; pc = CAP1; cap = CAP1; }
    const int* row = S + (size_t)k * pc;
    int lo = 0, hi = pc;
    while (lo < hi) {
        int mid = (lo + hi) >> 1;
        if (row[mid] == cap) hi = mid; else lo = mid + 1;
    }
    g_cnt[t] = lo;
}

// ---------------- input GEMM: fin = sp_feats[NIN,64] @ w_in[64,32] ----------------
__global__ void k_gemm_in(const float* __restrict__ sp, const float* __restrict__ w,
                          float* __restrict__ out) {
    int t = blockIdx.x * blockDim.x + threadIdx.x;
    if (t >= NIN * 32) return;
    int i = t >> 5, j = t & 31;
    const float* r = sp + i * 64;
    float acc = 0.f;
#pragma unroll
    for (int c = 0; c < 64; c++) acc += r[c] * w[c * 32 + j];
    out[t] = acc;
}

// ---------------- compacted gather-GEMM-scatter, weights in registers ----------------
// One warp per pair, grid-strided over the real prefix [0, cnt[k]).
// Lane owns output columns [lane*R, lane*R+R).
template<int CIN, int COUT, int NB>
__global__ void k_spconv2(const float* __restrict__ feats,
                          const int* __restrict__ G, const int* __restrict__ S,
                          const float* __restrict__ W, float* __restrict__ out,
                          int pair_cap, const int* __restrict__ cnt) {
    constexpr int R = COUT / 32;
    int k = blockIdx.x / NB;
    int lane = threadIdx.x & 31;
    float w[CIN * R];
    const float* Wk = W + (size_t)k * CIN * COUT;
#pragma unroll
    for (int c = 0; c < CIN; c++)
#pragma unroll
        for (int r = 0; r < R; r++)
            w[c * R + r] = Wk[c * COUT + lane * R + r];
    int n = cnt[k];
    int nw = blockDim.x >> 5;
    int p = (blockIdx.x % NB) * nw + (threadIdx.x >> 5);
    int stride = NB * nw;
    const int* Gk = G + (size_t)k * pair_cap;
    const int* Sk = S + (size_t)k * pair_cap;
    for (; p < n; p += stride) {
        int g = Gk[p], s = Sk[p];
        const float* fr = feats + (size_t)g * CIN;
        float fv[CIN / 32];
#pragma unroll
        for (int q = 0; q < CIN / 32; q++) fv[q] = fr[lane + 32 * q];
        float acc[R];
#pragma unroll
        for (int r = 0; r < R; r++) acc[r] = 0.f;
#pragma unroll
        for (int c = 0; c < CIN; c++) {
            float v = __shfl_sync(0xffffffffu, fv[c >> 5], c & 31);
#pragma unroll
            for (int r = 0; r < R; r++) acc[r] += v * w[c * R + r];
        }
        float* op = out + (size_t)s * COUT + lane * R;
        if constexpr (R == 1) {
            atomicAdd(op, acc[0]);
        } else {
            asm volatile("red.global.add.v2.f32 [%0], {%1, %2};"
                         :: "l"(op), "f"(acc[0]), "f"(acc[1]) : "memory");
        }
    }
}

// ---------------- BN1d + ReLU in place ----------------
__global__ void k_bnrelu(float* __restrict__ buf, const float* __restrict__ bn,
                         int rows, int C) {
    long long idx = (long long)blockIdx.x * blockDim.x + threadIdx.x;
    if (idx >= (long long)rows * C) return;
    int c = (int)(idx & (C - 1));
    float gg = bn[c], bb = bn[C + c], m = bn[2 * C + c], v = bn[3 * C + c];
    float x = buf[idx];
    float y = (x - m) * (gg * rsqrtf(v + EPSB)) + bb;
    buf[idx] = y > 0.f ? y : 0.f;
}

// ---------------- sparse -> dense scatter ----------------
__global__ void k_scatter0(const float* __restrict__ f, const int* __restrict__ co,
                           float* __restrict__ d0) {
    unsigned w = (blockIdx.x * blockDim.x + threadIdx.x) >> 5;
    int lane = threadIdx.x & 31;
    if (w >= CAP0) return;
    int z = co[4 * w + 1];
    if ((unsigned)z >= (unsigned)ZD) return;
    int b = co[4 * w], y = co[4 * w + 2], x = co[4 * w + 3];
    size_t base = ((size_t)(b * HW + y * XD + x)) * 320 + z * 32;
    d0[base + lane] = f[(size_t)w * 32 + lane];
}

__global__ void k_scatter1(const float* __restrict__ f, const int* __restrict__ co,
                           float* __restrict__ d1) {
    unsigned w = (blockIdx.x * blockDim.x + threadIdx.x) >> 5;
    int lane = threadIdx.x & 31;
    if (w >= CAP1) return;
    int z = co[4 * w + 1];
    if ((unsigned)z >= (unsigned)Z1D) return;
    int b = co[4 * w], y = co[4 * w + 2], x = co[4 * w + 3];
    size_t base = ((size_t)(b * HW1 + y * X1D + x)) * 320 + z * 64;
    d1[base + lane]      = f[(size_t)w * 64 + lane];
    d1[base + lane + 32] = f[(size_t)w * 64 + lane + 32];
}

// ---------------- weight permutes for dense GEMMs ----------------
// conv1x1 B: wp[kk=z*32+c][o]  from ct0_w[(c*10+z)][o]
__global__ void k_permw0(const float* __restrict__ w, float* __restrict__ wp) {
    int t = blockIdx.x * blockDim.x + threadIdx.x;
    if (t >= 320 * 64) return;
    int o = t & 63, kk = t >> 6;
    int z = kk >> 5, c = kk & 31;
    wp[t] = w[(c * 10 + z) * 64 + o];
}
// convt B: wp[kk=z*64+c][ij*64+o]  from ct1_w[(c*5+z)][o][i][j]
__global__ void k_permw1(const float* __restrict__ w, float* __restrict__ wp) {
    int t = blockIdx.x * blockDim.x + threadIdx.x;
    if (t >= 320 * 256) return;
    int col = t & 255, kk = t >> 8;
    int ij = col >> 6, o = col & 63;
    int z = kk >> 6, c = kk & 63;
    wp[t] = w[((c * 5 + z) * 64 + o) * 4 + ij];
}

// ---------------- tiled GEMM 64x64, K=320, 4x4 register blocking ----------------
// conv1x1: A = d0 [281600 x 320], B = w0p [320 x 64] -> bev0 with BN+ReLU
__global__ void k_gemm_bev0(const float* __restrict__ A, const float* __restrict__ B,
                            const float* __restrict__ bias, const float* __restrict__ bn,
                            float* __restrict__ bev) {
    __shared__ float As[16][72];
    __shared__ float Bs[16][64];
    int tid = threadIdx.x;
    int tx = tid & 15, ty = tid >> 4;
    int row0 = blockIdx.x * 64;
    float acc[4][4] = {};
    int lr = tid >> 2, lk = (tid & 3) * 4;
    int bk = tid >> 4, bc = (tid & 15) * 4;
    for (int k0 = 0; k0 < 320; k0 += 16) {
        float4 av = *(const float4*)(A + (size_t)(row0 + lr) * 320 + k0 + lk);
        As[lk + 0][lr] = av.x; As[lk + 1][lr] = av.y;
        As[lk + 2][lr] = av.z; As[lk + 3][lr] = av.w;
        *(float4*)&Bs[bk][bc] = *(const float4*)(B + (size_t)(k0 + bk) * 64 + bc);
        __syncthreads();
#pragma unroll
        for (int kk = 0; kk < 16; kk++) {
            float4 a4 = *(const float4*)&As[kk][ty * 4];
            float4 b4 = *(const float4*)&Bs[kk][tx * 4];
            float aa[4] = {a4.x, a4.y, a4.z, a4.w};
            float bb[4] = {b4.x, b4.y, b4.z, b4.w};
#pragma unroll
            for (int i = 0; i < 4; i++)
#pragma unroll
                for (int j = 0; j < 4; j++) acc[i][j] += aa[i] * bb[j];
        }
        __syncthreads();
    }
#pragma unroll
    for (int j = 0; j < 4; j++) {
        int o = tx * 4 + j;
        float sc = bn[o] * rsqrtf(bn[192 + o] + EPSB);
        float ofs = bn[64 + o] + (bias[o] - bn[128 + o]) * sc;
#pragma unroll
        for (int i = 0; i < 4; i++) {
            int r = row0 + ty * 4 + i;
            int b = r >= HW;
            int pp = r - b * HW;
            float y = acc[i][j] * sc + ofs;
            bev[(size_t)(b * 64 + o) * HW + pp] = fmaxf(y, 0.f);
        }
    }
}

// convt: A = d1 [70400 x 320], B = w1p [320 x 256], col tile = ij
__global__ void k_gemm_bev1(const float* __restrict__ A, const float* __restrict__ B,
                            const float* __restrict__ bias, const float* __restrict__ bn,
                            float* __restrict__ bev) {
    __shared__ float As[16][72];
    __shared__ float Bs[16][64];
    int tid = threadIdx.x;
    int tx = tid & 15, ty = tid >> 4;
    int row0 = blockIdx.x * 64;
    int colbase = blockIdx.y * 64;
    float acc[4][4] = {};
    int lr = tid >> 2, lk = (tid & 3) * 4;
    int bk = tid >> 4, bc = (tid & 15) * 4;
    for (int k0 = 0; k0 < 320; k0 += 16) {
        float4 av = *(const float4*)(A + (size_t)(row0 + lr) * 320 + k0 + lk);
        As[lk + 0][lr] = av.x; As[lk + 1][lr] = av.y;
        As[lk + 2][lr] = av.z; As[lk + 3][lr] = av.w;
        *(float4*)&Bs[bk][bc] = *(const float4*)(B + (size_t)(k0 + bk) * 256 + colbase + bc);
        __syncthreads();
#pragma unroll
        for (int kk = 0; kk < 16; kk++) {
            float4 a4 = *(const float4*)&As[kk][ty * 4];
            float4 b4 = *(const float4*)&Bs[kk][tx * 4];
            float aa[4] = {a4.x, a4.y, a4.z, a4.w};
            float bb[4] = {b4.x, b4.y, b4.z, b4.w};
#pragma unroll
            for (int i = 0; i < 4; i++)
#pragma unroll
                for (int j = 0; j < 4; j++) acc[i][j] += aa[i] * bb[j];
        }
        __syncthreads();
    }
    int ij = blockIdx.y, ii = ij >> 1, jj = ij & 1;
#pragma unroll
    for (int j = 0; j < 4; j++) {
        int o = tx * 4 + j;
        float sc = bn[o] * rsqrtf(bn[192 + o] + EPSB);
        float ofs = bn[64 + o] + (bias[o] - bn[128 + o]) * sc;
#pragma unroll
        for (int i = 0; i < 4; i++) {
            int r = row0 + ty * 4 + i;
            int b = r >= HW1;
            int p = r - b * HW1;
            int y = p / X1D, x = p - y * X1D;
            int opix = (2 * y + ii) * XD + 2 * x + jj;
            float val = acc[i][j] * sc + ofs;
            bev[(size_t)(b * 64 + o) * HW + opix] = fmaxf(val, 0.f);
        }
    }
}

// ---------------- per-pixel 2-agent attention fusion ----------------
__global__ void k_fusion(const float* __restrict__ bev, float* __restrict__ out, int cbase) {
    int p = blockIdx.x * blockDim.x + threadIdx.x;
    if (p >= HW) return;
    float l00 = 0.f, l01 = 0.f;
#pragma unroll 8
    for (int c = 0; c < 64; c++) {
        float x0 = bev[c * HW + p];
        float x1 = bev[(64 + c) * HW + p];
        l00 += x0 * x0;
        l01 += x0 * x1;
    }
    l00 *= 0.125f; l01 *= 0.125f;
    float mm = fmaxf(l00, l01);
    float e0 = expf(l00 - mm), e1 = expf(l01 - mm);
    float inv = 1.f / (e0 + e1);
    float a0 = e0 * inv, a1 = e1 * inv;
#pragma unroll 8
    for (int c = 0; c < 64; c++) {
        float x0 = bev[c * HW + p];
        float x1 = bev[(64 + c) * HW + p];
        out[(size_t)(cbase + c) * HW + p] = a0 * x0 + a1 * x1;
    }
}

// ---------------- host launcher ----------------
static inline unsigned blocks_for(long long threads, int bs) {
    return (unsigned)((threads + bs - 1) / bs);
}

extern "C" void kernel_launch(void* const* d_in, const int* in_sizes, int n_in,
                              void* d_out, int out_size) {
    const float* sp    = (const float*)d_in[0];
    const float* w_in  = (const float*)d_in[1];
    const float* w0    = (const float*)d_in[2];
    const float* bnp0  = (const float*)d_in[3];
    const float* w0a   = (const float*)d_in[4];
    const float* bnp0a = (const float*)d_in[5];
    const float* w0b   = (const float*)d_in[6];
    const float* bnp0b = (const float*)d_in[7];
    const float* w1    = (const float*)d_in[8];
    const float* bnp1  = (const float*)d_in[9];
    const float* w1a   = (const float*)d_in[10];
    const float* bnp1a = (const float*)d_in[11];
    const float* w1b   = (const float*)d_in[12];
    const float* bnp1b = (const float*)d_in[13];
    const float* ct0_w = (const float*)d_in[14];
    const float* ct0_b = (const float*)d_in[15];
    const float* bnt0  = (const float*)d_in[16];
    const float* ct1_w = (const float*)d_in[17];
    const float* ct1_b = (const float*)d_in[18];
    const float* bnt1  = (const float*)d_in[19];
    const int* coords0 = (const int*)d_in[20];
    const int* coords1 = (const int*)d_in[21];
    const int* g0      = (const int*)d_in[22];
    const int* s0      = (const int*)d_in[23];
    const int* ga      = (const int*)d_in[24];
    const int* sa      = (const int*)d_in[25];
    const int* g1      = (const int*)d_in[26];
    const int* s1      = (const int*)d_in[27];
    const int* gb      = (const int*)d_in[28];
    const int* sb      = (const int*)d_in[29];
    float* out = (float*)d_out;

    float *fin, *f0a, *f0b, *f1a, *f1b, *d0, *d1, *bev0, *bev1, *w0p, *w1p;
    int* cnt;
    cudaGetSymbolAddress((void**)&fin,  g_fin);
    cudaGetSymbolAddress((void**)&f0a,  g_f0a);
    cudaGetSymbolAddress((void**)&f0b,  g_f0b);
    cudaGetSymbolAddress((void**)&f1a,  g_f1a);
    cudaGetSymbolAddress((void**)&f1b,  g_f1b);
    cudaGetSymbolAddress((void**)&d0,   g_d0);
    cudaGetSymbolAddress((void**)&d1,   g_d1);
    cudaGetSymbolAddress((void**)&bev0, g_bev0);
    cudaGetSymbolAddress((void**)&bev1, g_bev1);
    cudaGetSymbolAddress((void**)&w0p,  g_w0p);
    cudaGetSymbolAddress((void**)&w1p,  g_w1p);
    cudaGetSymbolAddress((void**)&cnt,  g_cnt);

    const int BS = 256;

    // rulebook counts + input GEMM + weight permutes (independent, front-loaded)
    k_counts<<<1, 128>>>(s0, sa, s1, sb);
    k_gemm_in<<<blocks_for((long long)NIN * 32, BS), BS>>>(sp, w_in, fin);
    k_permw0<<<blocks_for(320 * 64, BS), BS>>>(ct0_w, w0p);
    k_permw1<<<blocks_for(320 * 256, BS), BS>>>(ct1_w, w1p);

    // ---- stage 0: spconv (stride1) + 2x subm, C=32 ----
    cudaMemsetAsync(f0a, 0, (size_t)(CAP0 + 1) * 32 * sizeof(float), 0);
    k_spconv2<32, 32, 16><<<27 * 16, 256>>>(fin, g0, s0, w0, f0a, NIN, cnt);
    k_bnrelu<<<blocks_for((long long)CAP0 * 32, BS), BS>>>(f0a, bnp0, CAP0, 32);

    cudaMemsetAsync(f0b, 0, (size_t)(CAP0 + 1) * 32 * sizeof(float), 0);
    k_spconv2<32, 32, 64><<<27 * 64, 256>>>(f0a, ga, sa, w0a, f0b, CAP0, cnt + 27);
    k_bnrelu<<<blocks_for((long long)CAP0 * 32, BS), BS>>>(f0b, bnp0a, CAP0, 32);

    cudaMemsetAsync(f0a, 0, (size_t)(CAP0 + 1) * 32 * sizeof(float), 0);
    k_spconv2<32, 32, 64><<<27 * 64, 256>>>(f0b, ga, sa, w0b, f0a, CAP0, cnt + 27);
    k_bnrelu<<<blocks_for((long long)CAP0 * 32, BS), BS>>>(f0a, bnp0b, CAP0, 32);

    // ---- dense BEV 0 ----
    cudaMemsetAsync(d0, 0, (size_t)2 * HW * 320 * sizeof(float), 0);
    k_scatter0<<<blocks_for((long long)CAP0 * 32, BS), BS>>>(f0a, coords0, d0);
    k_gemm_bev0<<<(2 * HW) / 64, 256>>>(d0, w0p, ct0_b, bnt0, bev0);
    k_fusion<<<blocks_for(HW, BS), BS>>>(bev0, out, 0);

    // ---- stage 1: spconv (stride2, 32->64) + 2x subm (64->64) ----
    cudaMemsetAsync(f1a, 0, (size_t)(CAP1 + 1) * 64 * sizeof(float), 0);
    k_spconv2<32, 64, 48><<<27 * 48, 256>>>(f0a, g1, s1, w1, f1a, CAP0, cnt + 54);
    k_bnrelu<<<blocks_for((long long)CAP1 * 64, BS), BS>>>(f1a, bnp1, CAP1, 64);

    cudaMemsetAsync(f1b, 0, (size_t)(CAP1 + 1) * 64 * sizeof(float), 0);
    k_spconv2<64, 64, 96><<<27 * 96, 128>>>(f1a, gb, sb, w1a, f1b, CAP1, cnt + 81);
    k_bnrelu<<<blocks_for((long long)CAP1 * 64, BS), BS>>>(f1b, bnp1a, CAP1, 64);

    cudaMemsetAsync(f1a, 0, (size_t)(CAP1 + 1) * 64 * sizeof(float), 0);
    k_spconv2<64, 64, 96><<<27 * 96, 128>>>(f1b, gb, sb, w1b, f1a, CAP1, cnt + 81);
    k_bnrelu<<<blocks_for((long long)CAP1 * 64, BS), BS>>>(f1a, bnp1b, CAP1, 64);

    // ---- dense BEV 1 ----
    cudaMemsetAsync(d1, 0, (size_t)2 * HW1 * 320 * sizeof(float), 0);
    k_scatter1<<<blocks_for((long long)CAP1 * 32, BS), BS>>>(f1a, coords1, d1);
    {
        dim3 grid((2 * HW1) / 64, 4);
        k_gemm_bev1<<<grid, 256>>>(d1, w1p, ct1_b, bnt1, bev1);
    }
    k_fusion<<<blocks_for(HW, BS), BS>>>(bev1, out, 64);
}

// round 3
// speedup vs baseline: 2.1292x; 1.1849x over previous
#include <cuda_runtime.h>
#include <math.h>

// ---------------- problem constants ----------------
#define NIN    20000          // B_AG * N_PTS
#define CAP0   540000         // 27 * NIN
#define CAP1   352000         // B_AG * Z1*Y1*X1
#define ZD     10
#define YD     200
#define XD     704
#define Z1D    5
#define Y1D    100
#define X1D    352
#define HW     (YD*XD)        // 140800
#define HW1    (Y1D*X1D)      // 35200
#define EPSB   1e-5f

// ---------------- static device scratch ----------------
__device__ float g_fin [NIN * 32];
__device__ float g_f0a [(CAP0 + 1) * 32];
__device__ float g_f0b [(CAP0 + 1) * 32];
__device__ float g_f1a [(CAP1 + 1) * 64];
__device__ float g_f1b [(CAP1 + 1) * 64];
__device__ float g_d0  [2 * HW  * 320];              // [b*HW+p][z*32+c]
__device__ float g_d1  [2 * HW1 * 320];              // [b*HW1+p][z*64+c]
__device__ float g_bev0[2 * 64 * HW];                // [b*64+o][p]
__device__ float g_bev1[2 * 64 * HW];
__device__ float g_w0p [320 * 64];                   // B for conv1x1 GEMM
__device__ float g_w1p [320 * 256];                  // B for convt GEMM [kk][ij*64+o]
__device__ int   g_cnt [108];                        // per-k real pair counts, 4 rulebooks

// ---------------- packed f32x2 helpers ----------------
__device__ __forceinline__ void fma2(unsigned long long& acc, unsigned long long a,
                                     unsigned long long b) {
    asm("fma.rn.f32x2 %0, %1, %2, %0;" : "+l"(acc) : "l"(a), "l"(b));
}
__device__ __forceinline__ void lds_2x64(unsigned long long& a, unsigned long long& b,
                                         unsigned addr) {
    asm volatile("ld.shared.v2.b64 {%0, %1}, [%2];" : "=l"(a), "=l"(b) : "r"(addr));
}
__device__ __forceinline__ void add2(unsigned long long& d, unsigned long long a,
                                     unsigned long long b) {
    asm("add.rn.f32x2 %0, %1, %2;" : "=l"(d) : "l"(a), "l"(b));
}
__device__ __forceinline__ void red2(float* p, unsigned long long acc) {
    float rx, ry;
    asm("mov.b64 {%0, %1}, %2;" : "=f"(rx), "=f"(ry) : "l"(acc));
    asm volatile("red.global.add.v2.f32 [%0], {%1, %2};" :: "l"(p), "f"(rx), "f"(ry)
                 : "memory");
}

// ---------------- rulebook pair counts (binary search on padded suffix) ----------------
__global__ void k_counts(const int* __restrict__ s0, const int* __restrict__ sa,
                         const int* __restrict__ s1, const int* __restrict__ sb) {
    int t = blockIdx.x * blockDim.x + threadIdx.x;
    if (t >= 108) return;
    int rb = t / 27, k = t % 27;
    const int* S; int pc, cap;
    if      (rb == 0) { S = s0; pc = NIN;  cap = CAP0; }
    else if (rb == 1) { S = sa; pc = CAP0; cap = CAP0; }
    else if (rb == 2) { S = s1; pc = CAP0; cap = CAP1; }
    else              { S = sb; pc = CAP1; cap = CAP1; }
    const int* row = S + (size_t)k * pc;
    int lo = 0, hi = pc;
    while (lo < hi) {
        int mid = (lo + hi) >> 1;
        if (row[mid] == cap) hi = mid; else lo = mid + 1;
    }
    g_cnt[t] = lo;
}

// ---------------- input GEMM: fin = sp_feats[NIN,64] @ w_in[64,32] ----------------
__global__ void k_gemm_in(const float* __restrict__ sp, const float* __restrict__ w,
                          float* __restrict__ out) {
    int t = blockIdx.x * blockDim.x + threadIdx.x;
    if (t >= NIN * 32) return;
    int i = t >> 5, j = t & 31;
    const float* r = sp + i * 64;
    float acc = 0.f;
#pragma unroll
    for (int c = 0; c < 64; c++) acc += r[c] * w[c * 32 + j];
    out[t] = acc;
}

// ---------------- spconv CIN=32 COUT=32: 2 pairs per warp (one per half-warp) ----------
// Features duplicated in smem; ld.shared.v2.b64 gives packed (v,v) operands; fma2.
template<int NB>
__global__ void __launch_bounds__(128) k_spconv32(
    const float* __restrict__ feats, const int* __restrict__ G, const int* __restrict__ S,
    const float* __restrict__ W, float* __restrict__ out, int pair_cap,
    const int* __restrict__ cnt) {
    __shared__ float slot[4][2][64];
    int k = blockIdx.x / NB;
    int lane = threadIdx.x & 31;
    int warp = threadIdx.x >> 5;
    int half = lane >> 4;
    int j = lane & 15;
    const float* Wk = W + (size_t)k * 1024;
    unsigned long long w2[32];
#pragma unroll
    for (int c = 0; c < 32; c++)
        w2[c] = *(const unsigned long long*)(Wk + c * 32 + 2 * j);
    int n = cnt[k];
    const int* Gk = G + (size_t)k * pair_cap;
    const int* Sk = S + (size_t)k * pair_cap;
    int base = ((blockIdx.x % NB) * 4 + warp) * 2;
    int stride = NB * 8;
    unsigned saddr = (unsigned)__cvta_generic_to_shared(&slot[warp][half][0]);
    for (int pb = base; pb < n; pb += stride) {
        int p = pb + half;
        bool act = p < n;
        int g = 0, s = 0;
        if (act) { g = Gk[p]; s = Sk[p]; }
        if (act && j < 8) {
            float4 f = *(const float4*)(feats + (size_t)g * 32 + 4 * j);
            *(float4*)&slot[warp][half][8 * j]     = make_float4(f.x, f.x, f.y, f.y);
            *(float4*)&slot[warp][half][8 * j + 4] = make_float4(f.z, f.z, f.w, f.w);
        }
        __syncwarp();
        unsigned long long acc0 = 0ull, acc1 = 0ull;
#pragma unroll
        for (int c2 = 0; c2 < 16; c2++) {
            unsigned long long va, vb;
            lds_2x64(va, vb, saddr + c2 * 16);
            fma2(acc0, va, w2[2 * c2]);
            fma2(acc1, vb, w2[2 * c2 + 1]);
        }
        __syncwarp();
        if (act) {
            unsigned long long acc;
            add2(acc, acc0, acc1);
            red2(out + (size_t)s * 32 + 2 * j, acc);
        }
    }
}

// ---------------- spconv CIN=32 COUT=64: warp per pair, lane owns 2 cols ----------------
template<int NB>
__global__ void __launch_bounds__(128) k_spconv3264(
    const float* __restrict__ feats, const int* __restrict__ G, const int* __restrict__ S,
    const float* __restrict__ W, float* __restrict__ out, int pair_cap,
    const int* __restrict__ cnt) {
    __shared__ float slot[4][64];
    int k = blockIdx.x / NB;
    int lane = threadIdx.x & 31;
    int warp = threadIdx.x >> 5;
    const float* Wk = W + (size_t)k * 2048;
    unsigned long long w2[32];
#pragma unroll
    for (int c = 0; c < 32; c++)
        w2[c] = *(const unsigned long long*)(Wk + c * 64 + 2 * lane);
    int n = cnt[k];
    const int* Gk = G + (size_t)k * pair_cap;
    const int* Sk = S + (size_t)k * pair_cap;
    int base = (blockIdx.x % NB) * 4 + warp;
    int stride = NB * 4;
    unsigned saddr = (unsigned)__cvta_generic_to_shared(&slot[warp][0]);
    for (int p = base; p < n; p += stride) {
        int g = Gk[p], s = Sk[p];
        if (lane < 8) {
            float4 f = *(const float4*)(feats + (size_t)g * 32 + 4 * lane);
            *(float4*)&slot[warp][8 * lane]     = make_float4(f.x, f.x, f.y, f.y);
            *(float4*)&slot[warp][8 * lane + 4] = make_float4(f.z, f.z, f.w, f.w);
        }
        __syncwarp();
        unsigned long long acc0 = 0ull, acc1 = 0ull;
#pragma unroll
        for (int c2 = 0; c2 < 16; c2++) {
            unsigned long long va, vb;
            lds_2x64(va, vb, saddr + c2 * 16);
            fma2(acc0, va, w2[2 * c2]);
            fma2(acc1, vb, w2[2 * c2 + 1]);
        }
        __syncwarp();
        unsigned long long acc;
        add2(acc, acc0, acc1);
        red2(out + (size_t)s * 64 + 2 * lane, acc);
    }
}

// ---------------- spconv CIN=64 COUT=64: warp per pair, lane owns 2 cols ----------------
template<int NB>
__global__ void __launch_bounds__(128) k_spconv64(
    const float* __restrict__ feats, const int* __restrict__ G, const int* __restrict__ S,
    const float* __restrict__ W, float* __restrict__ out, int pair_cap,
    const int* __restrict__ cnt) {
    __shared__ float slot[4][128];
    int k = blockIdx.x / NB;
    int lane = threadIdx.x & 31;
    int warp = threadIdx.x >> 5;
    const float* Wk = W + (size_t)k * 4096;
    unsigned long long w2[64];
#pragma unroll
    for (int c = 0; c < 64; c++)
        w2[c] = *(const unsigned long long*)(Wk + c * 64 + 2 * lane);
    int n = cnt[k];
    const int* Gk = G + (size_t)k * pair_cap;
    const int* Sk = S + (size_t)k * pair_cap;
    int base = (blockIdx.x % NB) * 4 + warp;
    int stride = NB * 4;
    unsigned saddr = (unsigned)__cvta_generic_to_shared(&slot[warp][0]);
    for (int p = base; p < n; p += stride) {
        int g = Gk[p], s = Sk[p];
        {
            float2 f = *(const float2*)(feats + (size_t)g * 64 + 2 * lane);
            *(float4*)&slot[warp][4 * lane] = make_float4(f.x, f.x, f.y, f.y);
        }
        __syncwarp();
        unsigned long long acc0 = 0ull, acc1 = 0ull;
#pragma unroll
        for (int c2 = 0; c2 < 32; c2++) {
            unsigned long long va, vb;
            lds_2x64(va, vb, saddr + c2 * 16);
            fma2(acc0, va, w2[2 * c2]);
            fma2(acc1, vb, w2[2 * c2 + 1]);
        }
        __syncwarp();
        unsigned long long acc;
        add2(acc, acc0, acc1);
        red2(out + (size_t)s * 64 + 2 * lane, acc);
    }
}

// ---------------- BN1d + ReLU in place, float4 ----------------
__global__ void k_bnrelu4(float* __restrict__ buf, const float* __restrict__ bn,
                          long long n4, int C) {
    long long idx = (long long)blockIdx.x * blockDim.x + threadIdx.x;
    if (idx >= n4) return;
    int c = (int)((idx * 4) & (C - 1));
    float4 x = ((float4*)buf)[idx];
    float4 gg = *(const float4*)(bn + c);
    float4 bb = *(const float4*)(bn + C + c);
    float4 mm = *(const float4*)(bn + 2 * C + c);
    float4 vv = *(const float4*)(bn + 3 * C + c);
    float4 y;
    y.x = fmaxf((x.x - mm.x) * (gg.x * rsqrtf(vv.x + EPSB)) + bb.x, 0.f);
    y.y = fmaxf((x.y - mm.y) * (gg.y * rsqrtf(vv.y + EPSB)) + bb.y, 0.f);
    y.z = fmaxf((x.z - mm.z) * (gg.z * rsqrtf(vv.z + EPSB)) + bb.z, 0.f);
    y.w = fmaxf((x.w - mm.w) * (gg.w * rsqrtf(vv.w + EPSB)) + bb.w, 0.f);
    ((float4*)buf)[idx] = y;
}

// ---------------- sparse -> dense scatter ----------------
__global__ void k_scatter0(const float* __restrict__ f, const int* __restrict__ co,
                           float* __restrict__ d0) {
    unsigned w = (blockIdx.x * blockDim.x + threadIdx.x) >> 5;
    int lane = threadIdx.x & 31;
    if (w >= CAP0) return;
    int z = co[4 * w + 1];
    if ((unsigned)z >= (unsigned)ZD) return;
    int b = co[4 * w], y = co[4 * w + 2], x = co[4 * w + 3];
    size_t base = ((size_t)(b * HW + y * XD + x)) * 320 + z * 32;
    d0[base + lane] = f[(size_t)w * 32 + lane];
}

__global__ void k_scatter1(const float* __restrict__ f, const int* __restrict__ co,
                           float* __restrict__ d1) {
    unsigned w = (blockIdx.x * blockDim.x + threadIdx.x) >> 5;
    int lane = threadIdx.x & 31;
    if (w >= CAP1) return;
    int z = co[4 * w + 1];
    if ((unsigned)z >= (unsigned)Z1D) return;
    int b = co[4 * w], y = co[4 * w + 2], x = co[4 * w + 3];
    size_t base = ((size_t)(b * HW1 + y * X1D + x)) * 320 + z * 64;
    d1[base + lane]      = f[(size_t)w * 64 + lane];
    d1[base + lane + 32] = f[(size_t)w * 64 + lane + 32];
}

// ---------------- weight permutes for dense GEMMs ----------------
__global__ void k_permw0(const float* __restrict__ w, float* __restrict__ wp) {
    int t = blockIdx.x * blockDim.x + threadIdx.x;
    if (t >= 320 * 64) return;
    int o = t & 63, kk = t >> 6;
    int z = kk >> 5, c = kk & 31;
    wp[t] = w[(c * 10 + z) * 64 + o];
}
__global__ void k_permw1(const float* __restrict__ w, float* __restrict__ wp) {
    int t = blockIdx.x * blockDim.x + threadIdx.x;
    if (t >= 320 * 256) return;
    int col = t & 255, kk = t >> 8;
    int ij = col >> 6, o = col & 63;
    int z = kk >> 6, c = kk & 63;
    wp[t] = w[((c * 5 + z) * 64 + o) * 4 + ij];
}

// ---------------- tiled GEMM 64x64, K=320, 4x4 register blocking ----------------
__global__ void k_gemm_bev0(const float* __restrict__ A, const float* __restrict__ B,
                            const float* __restrict__ bias, const float* __restrict__ bn,
                            float* __restrict__ bev) {
    __shared__ float As[16][72];
    __shared__ float Bs[16][64];
    int tid = threadIdx.x;
    int tx = tid & 15, ty = tid >> 4;
    int row0 = blockIdx.x * 64;
    float acc[4][4] = {};
    int lr = tid >> 2, lk = (tid & 3) * 4;
    int bk = tid >> 4, bc = (tid & 15) * 4;
    for (int k0 = 0; k0 < 320; k0 += 16) {
        float4 av = *(const float4*)(A + (size_t)(row0 + lr) * 320 + k0 + lk);
        As[lk + 0][lr] = av.x; As[lk + 1][lr] = av.y;
        As[lk + 2][lr] = av.z; As[lk + 3][lr] = av.w;
        *(float4*)&Bs[bk][bc] = *(const float4*)(B + (size_t)(k0 + bk) * 64 + bc);
        __syncthreads();
#pragma unroll
        for (int kk = 0; kk < 16; kk++) {
            float4 a4 = *(const float4*)&As[kk][ty * 4];
            float4 b4 = *(const float4*)&Bs[kk][tx * 4];
            float aa[4] = {a4.x, a4.y, a4.z, a4.w};
            float bb[4] = {b4.x, b4.y, b4.z, b4.w};
#pragma unroll
            for (int i = 0; i < 4; i++)
#pragma unroll
                for (int j = 0; j < 4; j++) acc[i][j] += aa[i] * bb[j];
        }
        __syncthreads();
    }
#pragma unroll
    for (int j = 0; j < 4; j++) {
        int o = tx * 4 + j;
        float sc = bn[o] * rsqrtf(bn[192 + o] + EPSB);
        float ofs = bn[64 + o] + (bias[o] - bn[128 + o]) * sc;
#pragma unroll
        for (int i = 0; i < 4; i++) {
            int r = row0 + ty * 4 + i;
            int b = r >= HW;
            int pp = r - b * HW;
            float y = acc[i][j] * sc + ofs;
            bev[(size_t)(b * 64 + o) * HW + pp] = fmaxf(y, 0.f);
        }
    }
}

__global__ void k_gemm_bev1(const float* __restrict__ A, const float* __restrict__ B,
                            const float* __restrict__ bias, const float* __restrict__ bn,
                            float* __restrict__ bev) {
    __shared__ float As[16][72];
    __shared__ float Bs[16][64];
    int tid = threadIdx.x;
    int tx = tid & 15, ty = tid >> 4;
    int row0 = blockIdx.x * 64;
    int colbase = blockIdx.y * 64;
    float acc[4][4] = {};
    int lr = tid >> 2, lk = (tid & 3) * 4;
    int bk = tid >> 4, bc = (tid & 15) * 4;
    for (int k0 = 0; k0 < 320; k0 += 16) {
        float4 av = *(const float4*)(A + (size_t)(row0 + lr) * 320 + k0 + lk);
        As[lk + 0][lr] = av.x; As[lk + 1][lr] = av.y;
        As[lk + 2][lr] = av.z; As[lk + 3][lr] = av.w;
        *(float4*)&Bs[bk][bc] = *(const float4*)(B + (size_t)(k0 + bk) * 256 + colbase + bc);
        __syncthreads();
#pragma unroll
        for (int kk = 0; kk < 16; kk++) {
            float4 a4 = *(const float4*)&As[kk][ty * 4];
            float4 b4 = *(const float4*)&Bs[kk][tx * 4];
            float aa[4] = {a4.x, a4.y, a4.z, a4.w};
            float bb[4] = {b4.x, b4.y, b4.z, b4.w};
#pragma unroll
            for (int i = 0; i < 4; i++)
#pragma unroll
                for (int j = 0; j < 4; j++) acc[i][j] += aa[i] * bb[j];
        }
        __syncthreads();
    }
    int ij = blockIdx.y, ii = ij >> 1, jj = ij & 1;
#pragma unroll
    for (int j = 0; j < 4; j++) {
        int o = tx * 4 + j;
        float sc = bn[o] * rsqrtf(bn[192 + o] + EPSB);
        float ofs = bn[64 + o] + (bias[o] - bn[128 + o]) * sc;
#pragma unroll
        for (int i = 0; i < 4; i++) {
            int r = row0 + ty * 4 + i;
            int b = r >= HW1;
            int p = r - b * HW1;
            int y = p / X1D, x = p - y * X1D;
            int opix = (2 * y + ii) * XD + 2 * x + jj;
            float val = acc[i][j] * sc + ofs;
            bev[(size_t)(b * 64 + o) * HW + opix] = fmaxf(val, 0.f);
        }
    }
}

// ---------------- per-pixel 2-agent attention fusion ----------------
__global__ void k_fusion(const float* __restrict__ bev, float* __restrict__ out, int cbase) {
    int p = blockIdx.x * blockDim.x + threadIdx.x;
    if (p >= HW) return;
    float l00 = 0.f, l01 = 0.f;
#pragma unroll 8
    for (int c = 0; c < 64; c++) {
        float x0 = bev[c * HW + p];
        float x1 = bev[(64 + c) * HW + p];
        l00 += x0 * x0;
        l01 += x0 * x1;
    }
    l00 *= 0.125f; l01 *= 0.125f;
    float mm = fmaxf(l00, l01);
    float e0 = expf(l00 - mm), e1 = expf(l01 - mm);
    float inv = 1.f / (e0 + e1);
    float a0 = e0 * inv, a1 = e1 * inv;
#pragma unroll 8
    for (int c = 0; c < 64; c++) {
        float x0 = bev[c * HW + p];
        float x1 = bev[(64 + c) * HW + p];
        out[(size_t)(cbase + c) * HW + p] = a0 * x0 + a1 * x1;
    }
}

// ---------------- host launcher ----------------
static inline unsigned blocks_for(long long threads, int bs) {
    return (unsigned)((threads + bs - 1) / bs);
}

extern "C" void kernel_launch(void* const* d_in, const int* in_sizes, int n_in,
                              void* d_out, int out_size) {
    const float* sp    = (const float*)d_in[0];
    const float* w_in  = (const float*)d_in[1];
    const float* w0    = (const float*)d_in[2];
    const float* bnp0  = (const float*)d_in[3];
    const float* w0a   = (const float*)d_in[4];
    const float* bnp0a = (const float*)d_in[5];
    const float* w0b   = (const float*)d_in[6];
    const float* bnp0b = (const float*)d_in[7];
    const float* w1    = (const float*)d_in[8];
    const float* bnp1  = (const float*)d_in[9];
    const float* w1a   = (const float*)d_in[10];
    const float* bnp1a = (const float*)d_in[11];
    const float* w1b   = (const float*)d_in[12];
    const float* bnp1b = (const float*)d_in[13];
    const float* ct0_w = (const float*)d_in[14];
    const float* ct0_b = (const float*)d_in[15];
    const float* bnt0  = (const float*)d_in[16];
    const float* ct1_w = (const float*)d_in[17];
    const float* ct1_b = (const float*)d_in[18];
    const float* bnt1  = (const float*)d_in[19];
    const int* coords0 = (const int*)d_in[20];
    const int* coords1 = (const int*)d_in[21];
    const int* g0      = (const int*)d_in[22];
    const int* s0      = (const int*)d_in[23];
    const int* ga      = (const int*)d_in[24];
    const int* sa      = (const int*)d_in[25];
    const int* g1      = (const int*)d_in[26];
    const int* s1      = (const int*)d_in[27];
    const int* gb      = (const int*)d_in[28];
    const int* sb      = (const int*)d_in[29];
    float* out = (float*)d_out;

    float *fin, *f0a, *f0b, *f1a, *f1b, *d0, *d1, *bev0, *bev1, *w0p, *w1p;
    int* cnt;
    cudaGetSymbolAddress((void**)&fin,  g_fin);
    cudaGetSymbolAddress((void**)&f0a,  g_f0a);
    cudaGetSymbolAddress((void**)&f0b,  g_f0b);
    cudaGetSymbolAddress((void**)&f1a,  g_f1a);
    cudaGetSymbolAddress((void**)&f1b,  g_f1b);
    cudaGetSymbolAddress((void**)&d0,   g_d0);
    cudaGetSymbolAddress((void**)&d1,   g_d1);
    cudaGetSymbolAddress((void**)&bev0, g_bev0);
    cudaGetSymbolAddress((void**)&bev1, g_bev1);
    cudaGetSymbolAddress((void**)&w0p,  g_w0p);
    cudaGetSymbolAddress((void**)&w1p,  g_w1p);
    cudaGetSymbolAddress((void**)&cnt,  g_cnt);

    const int BS = 256;

    // independent front-loaded work
    k_counts<<<1, 128>>>(s0, sa, s1, sb);
    k_gemm_in<<<blocks_for((long long)NIN * 32, BS), BS>>>(sp, w_in, fin);
    k_permw0<<<blocks_for(320 * 64, BS), BS>>>(ct0_w, w0p);
    k_permw1<<<blocks_for(320 * 256, BS), BS>>>(ct1_w, w1p);

    // ---- stage 0: spconv (stride1) + 2x subm, C=32 ----
    cudaMemsetAsync(f0a, 0, (size_t)(CAP0 + 1) * 32 * sizeof(float), 0);
    k_spconv32<16><<<27 * 16, 128>>>(fin, g0, s0, w0, f0a, NIN, cnt);
    k_bnrelu4<<<blocks_for((long long)CAP0 * 8, BS), BS>>>(f0a, bnp0, (long long)CAP0 * 8, 32);

    cudaMemsetAsync(f0b, 0, (size_t)(CAP0 + 1) * 32 * sizeof(float), 0);
    k_spconv32<96><<<27 * 96, 128>>>(f0a, ga, sa, w0a, f0b, CAP0, cnt + 27);
    k_bnrelu4<<<blocks_for((long long)CAP0 * 8, BS), BS>>>(f0b, bnp0a, (long long)CAP0 * 8, 32);

    cudaMemsetAsync(f0a, 0, (size_t)(CAP0 + 1) * 32 * sizeof(float), 0);
    k_spconv32<96><<<27 * 96, 128>>>(f0b, ga, sa, w0b, f0a, CAP0, cnt + 27);
    k_bnrelu4<<<blocks_for((long long)CAP0 * 8, BS), BS>>>(f0a, bnp0b, (long long)CAP0 * 8, 32);

    // ---- dense BEV 0 ----
    cudaMemsetAsync(d0, 0, (size_t)2 * HW * 320 * sizeof(float), 0);
    k_scatter0<<<blocks_for((long long)CAP0 * 32, BS), BS>>>(f0a, coords0, d0);
    k_gemm_bev0<<<(2 * HW) / 64, 256>>>(d0, w0p, ct0_b, bnt0, bev0);
    k_fusion<<<blocks_for(HW, BS), BS>>>(bev0, out, 0);

    // ---- stage 1: spconv (stride2, 32->64) + 2x subm (64->64) ----
    cudaMemsetAsync(f1a, 0, (size_t)(CAP1 + 1) * 64 * sizeof(float), 0);
    k_spconv3264<48><<<27 * 48, 128>>>(f0a, g1, s1, w1, f1a, CAP0, cnt + 54);
    k_bnrelu4<<<blocks_for((long long)CAP1 * 16, BS), BS>>>(f1a, bnp1, (long long)CAP1 * 16, 64);

    cudaMemsetAsync(f1b, 0, (size_t)(CAP1 + 1) * 64 * sizeof(float), 0);
    k_spconv64<64><<<27 * 64, 128>>>(f1a, gb, sb, w1a, f1b, CAP1, cnt + 81);
    k_bnrelu4<<<blocks_for((long long)CAP1 * 16, BS), BS>>>(f1b, bnp1a, (long long)CAP1 * 16, 64);

    cudaMemsetAsync(f1a, 0, (size_t)(CAP1 + 1) * 64 * sizeof(float), 0);
    k_spconv64<64><<<27 * 64, 128>>>(f1b, gb, sb, w1b, f1a, CAP1, cnt + 81);
    k_bnrelu4<<<blocks_for((long long)CAP1 * 16, BS), BS>>>(f1a, bnp1b, (long long)CAP1 * 16, 64);

    // ---- dense BEV 1 ----
    cudaMemsetAsync(d1, 0, (size_t)2 * HW1 * 320 * sizeof(float), 0);
    k_scatter1<<<blocks_for((long long)CAP1 * 32, BS), BS>>>(f1a, coords1, d1);
    {
        dim3 grid((2 * HW1) / 64, 4);
        k_gemm_bev1<<<grid, 256>>>(d1, w1p, ct1_b, bnt1, bev1);
    }
    k_fusion<<<blocks_for(HW, BS), BS>>>(bev1, out, 64);
}